// round 2
// baseline (speedup 1.0000x reference)
#include <cuda_runtime.h>
#include <math.h>
#include <stdint.h>

#define NTH 512
#define TILE 32
#define MC 32
#define NCH 8           // 256 / MC

typedef unsigned long long ull;

__device__ __forceinline__ ull pk2(float lo, float hi) {
    ull r; asm("mov.b64 %0,{%1,%2};" : "=l"(r) : "f"(lo), "f"(hi)); return r;
}
__device__ __forceinline__ void upk2(ull v, float &lo, float &hi) {
    asm("mov.b64 {%0,%1},%2;" : "=f"(lo), "=f"(hi) : "l"(v));
}
__device__ __forceinline__ void fma2(ull &d, ull a, ull b) {
    asm("fma.rn.f32x2 %0,%1,%2,%0;" : "+l"(d) : "l"(a), "l"(b));
}
__device__ __forceinline__ float silu_f(float v) { return v / (1.0f + __expf(-v)); }

__device__ __forceinline__ uint32_t s2u(const void *p) {
    uint32_t a;
    asm("{.reg .u64 t; cvta.to.shared.u64 t,%1; cvt.u32.u64 %0,t;}" : "=r"(a) : "l"(p));
    return a;
}
__device__ __forceinline__ void cpa16(uint32_t s, const void *g) {
    asm volatile("cp.async.cg.shared.global [%0],[%1],16;" :: "r"(s), "l"(g));
}
__device__ __forceinline__ void cpcommit() { asm volatile("cp.async.commit_group;"); }
template <int N> __device__ __forceinline__ void cpwait() {
    asm volatile("cp.async.wait_group %0;" :: "n"(N));
}

// smem float offsets
#define O_SXS 0          // [32][256]                 8192
#define O_SXV 8192       // [32][3][256] (i,m transposed)  24576
#define O_CWS 32768      // 2 x [32][128]             8192
#define O_CWV 40960      // 2 x [32][64]              4096
#define O_SHS 45056      // [32][128]                 4096
#define O_SHV 49152      // [3][32][64]               6144
#define SMEM_FLOATS 55296   // 221184 bytes

__global__ __launch_bounds__(NTH, 1)
void fused_dipole_v2(const float* __restrict__ x,
                     const float* __restrict__ w1s,
                     const float* __restrict__ w1v,
                     const float* __restrict__ w2s,
                     const float* __restrict__ w2v,
                     float* __restrict__ out,
                     int nrows)
{
    extern __shared__ float sm[];
    float* sxs = sm + O_SXS;
    float* sxv = sm + O_SXV;
    float* cws = sm + O_CWS;
    float* cwv = sm + O_CWV;
    float* shs = sm + O_SHS;
    float* shv = sm + O_SHV;

    const int tid = threadIdx.x;
    const int wid = tid >> 5;
    const int tx  = tid & 31;
    const int r0  = blockIdx.x * TILE;

    // ---- prefetch weight chunk 0 (cp.async, overlaps x staging) ----
    {
        const float4* gs = (const float4*)w1s;   // chunk 0: f4 [0,1024)
        const float4* gv = (const float4*)w1v;   // chunk 0: f4 [0,512)
        for (int t = tid; t < 1536; t += NTH) {
            if (t < 1024) cpa16(s2u(cws + t * 4), gs + t);
            else          cpa16(s2u(cwv + (t - 1024) * 4), gv + (t - 1024));
        }
        cpcommit();
    }

    // ---- stage x tile: xs linear, xv transposed to [r][i][m] ----
    {
        const float4* xg = (const float4*)x + (size_t)r0 * 256;
        #pragma unroll
        for (int it = 0; it < 16; ++it) {
            int idx = tid + it * NTH;        // 0..8191
            int r = idx >> 8, c4 = idx & 255;
            float4 v = xg[(size_t)r * 256 + c4];
            if (c4 < 64) {
                *(float4*)(sxs + r * 256 + c4 * 4) = v;
            } else {
                int cb = c4 * 4 - 256;       // 0..767
                float vv[4] = {v.x, v.y, v.z, v.w};
                #pragma unroll
                for (int q = 0; q < 4; ++q) {
                    int mc = cb + q;
                    int m = mc / 3, i = mc - 3 * m;
                    sxv[(r * 3 + i) * 256 + m] = vv[q];
                }
            }
        }
    }

    // role indices
    const int cg  = wid & 1;             // S: col group
    const int rg8 = (wid >> 1) * 8;      // S: first row
    const int jS  = cg * 64 + 2 * tx;    // S: 2 adjacent cols
    const int vw  = wid - 8;             // V role
    const int vr0 = vw * 4;              // V: first row (4 rows)
    const int jV  = 2 * tx;              // V: 2 adjacent cols

    ull acc[24];
    #pragma unroll
    for (int k = 0; k < 24; ++k) acc[k] = 0ull;

    // ---- m-chunk loop, double-buffered weights ----
    for (int ck = 0; ck < NCH; ++ck) {
        int nxt = ck + 1;
        if (nxt < NCH) {
            const float4* gs = (const float4*)w1s + nxt * 1024;
            const float4* gv = (const float4*)w1v + nxt * 512;
            float* dws = cws + (nxt & 1) * 4096;
            float* dwv = cwv + (nxt & 1) * 2048;
            for (int t = tid; t < 1536; t += NTH) {
                if (t < 1024) cpa16(s2u(dws + t * 4), gs + t);
                else          cpa16(s2u(dwv + (t - 1024) * 4), gv + (t - 1024));
            }
            cpcommit();
            cpwait<1>();
        } else {
            cpwait<0>();
        }
        __syncthreads();

        const float* bws = cws + (ck & 1) * 4096;
        const float* bwv = cwv + (ck & 1) * 2048;
        const int mbase = ck * MC;

        if (wid < 8) {
            // ===== scalar GEMM: 8 rows x 2 cols, m packed in pairs =====
            #pragma unroll 2
            for (int mm = 0; mm < MC; mm += 4) {
                ulonglong2 A[8];
                #pragma unroll
                for (int r = 0; r < 8; ++r)
                    A[r] = *(const ulonglong2*)(sxs + (rg8 + r) * 256 + mbase + mm);
                #pragma unroll
                for (int p = 0; p < 2; ++p) {
                    float2 a = *(const float2*)(bws + (mm + 2 * p) * 128 + jS);
                    float2 b = *(const float2*)(bws + (mm + 2 * p + 1) * 128 + jS);
                    ull P0 = pk2(a.x, b.x);
                    ull P1 = pk2(a.y, b.y);
                    #pragma unroll
                    for (int r = 0; r < 8; ++r) {
                        ull Ar = p ? A[r].y : A[r].x;
                        fma2(acc[r * 2 + 0], Ar, P0);
                        fma2(acc[r * 2 + 1], Ar, P1);
                    }
                }
            }
        } else {
            // ===== vector GEMM: 4 rows x 3 comps x 2 cols =====
            #pragma unroll 2
            for (int mm = 0; mm < MC; mm += 4) {
                ull P[2][2];
                #pragma unroll
                for (int p = 0; p < 2; ++p) {
                    float2 a = *(const float2*)(bwv + (mm + 2 * p) * 64 + jV);
                    float2 b = *(const float2*)(bwv + (mm + 2 * p + 1) * 64 + jV);
                    P[p][0] = pk2(a.x, b.x);
                    P[p][1] = pk2(a.y, b.y);
                }
                #pragma unroll
                for (int r = 0; r < 4; ++r) {
                    #pragma unroll
                    for (int i = 0; i < 3; ++i) {
                        ulonglong2 A = *(const ulonglong2*)(sxv + ((vr0 + r) * 3 + i) * 256 + mbase + mm);
                        int a0 = (r * 3 + i) * 2;
                        fma2(acc[a0 + 0], A.x, P[0][0]);
                        fma2(acc[a0 + 1], A.x, P[0][1]);
                        fma2(acc[a0 + 0], A.y, P[1][0]);
                        fma2(acc[a0 + 1], A.y, P[1][1]);
                    }
                }
            }
        }
        __syncthreads();   // protect weight buffer reuse next iter
    }

    // ---- store h to smem ----
    const float inv_in = 1.0f / 16.0f;
    if (wid < 8) {
        #pragma unroll
        for (int r = 0; r < 8; ++r)
            #pragma unroll
            for (int c = 0; c < 2; ++c) {
                float lo, hi; upk2(acc[r * 2 + c], lo, hi);
                shs[(rg8 + r) * 128 + jS + c] = (lo + hi) * inv_in;
            }
    } else {
        #pragma unroll
        for (int r = 0; r < 4; ++r)
            #pragma unroll
            for (int i = 0; i < 3; ++i)
                #pragma unroll
                for (int c = 0; c < 2; ++c) {
                    float lo, hi; upk2(acc[(r * 3 + i) * 2 + c], lo, hi);
                    shv[i * 2048 + (vr0 + r) * 64 + jV + c] = (lo + hi) * inv_in;
                }
    }
    __syncthreads();

    // ---- epilogue: 16 warps x 2 rows ----
    const float inv_h = 0.125f;
    const float ws0 = __ldg(w2s + tx),      ws1 = __ldg(w2s + 32 + tx);
    const float wv0 = __ldg(w2v + tx),      wv1 = __ldg(w2v + 32 + tx);
    #pragma unroll
    for (int rr = 0; rr < 2; ++rr) {
        int r  = wid * 2 + rr;
        int gr = r0 + r;
        const float* hrow = shs + r * 128;
        float s0  = hrow[tx];
        float s1  = hrow[32 + tx];
        float gt0 = hrow[64 + tx];
        float gt1 = hrow[96 + tx];
        float os  = silu_f(s0) * ws0 + silu_f(s1) * ws1;
        float sg0 = silu_f(gt0) * wv0;
        float sg1 = silu_f(gt1) * wv1;
        float ov0 = sg0 * shv[0 * 2048 + r * 64 + tx] + sg1 * shv[0 * 2048 + r * 64 + 32 + tx];
        float ov1 = sg0 * shv[1 * 2048 + r * 64 + tx] + sg1 * shv[1 * 2048 + r * 64 + 32 + tx];
        float ov2 = sg0 * shv[2 * 2048 + r * 64 + tx] + sg1 * shv[2 * 2048 + r * 64 + 32 + tx];
        #pragma unroll
        for (int off = 16; off > 0; off >>= 1) {
            os  += __shfl_xor_sync(0xffffffffu, os,  off);
            ov0 += __shfl_xor_sync(0xffffffffu, ov0, off);
            ov1 += __shfl_xor_sync(0xffffffffu, ov1, off);
            ov2 += __shfl_xor_sync(0xffffffffu, ov2, off);
        }
        if (tx == 0 && gr < nrows) {
            ((float4*)out)[gr] = make_float4(os * inv_h, ov0 * inv_h, ov1 * inv_h, ov2 * inv_h);
        }
    }
}

extern "C" void kernel_launch(void* const* d_in, const int* in_sizes, int n_in,
                              void* d_out, int out_size)
{
    const float* x   = (const float*)d_in[0];
    const float* w1s = (const float*)d_in[1];
    const float* w1v = (const float*)d_in[2];
    const float* w2s = (const float*)d_in[3];
    const float* w2v = (const float*)d_in[4];
    float* out = (float*)d_out;

    int nrows  = in_sizes[0] / 1024;
    int blocks = (nrows + TILE - 1) / TILE;   // 3125, exact
    size_t smem_bytes = (size_t)SMEM_FLOATS * sizeof(float);   // 221184

    cudaFuncSetAttribute(fused_dipole_v2,
                         cudaFuncAttributeMaxDynamicSharedMemorySize, (int)smem_bytes);
    fused_dipole_v2<<<blocks, NTH, smem_bytes>>>(x, w1s, w1v, w2s, w2v, out, nrows);
}

// round 5
// speedup vs baseline: 1.3212x; 1.3212x over previous
#include <cuda_runtime.h>
#include <cuda_bf16.h>
#include <stdint.h>

#define NTH 256
#define TILE_M 64
#define NCH 4

// smem byte offsets (all 16B aligned). A/Av rows padded: 64 bf16 + 8 pad = 144B.
// Bs rows: 128 bf16 + 8 pad = 272B. Bv rows: 144B. g: [64][65] f32.
#define SM_AS_H 0
#define SM_AS_L 9216
#define SM_AV_H 18432
#define SM_AV_L 46080
#define SM_BS_H 73728
#define SM_BS_L 91136
#define SM_BV_H 108544
#define SM_BV_L 117760
#define SM_G    126976
#define SM_TOTAL (126976 + 64*65*4)   // 143616

__device__ __forceinline__ uint32_t s2u(const void* p) {
    uint32_t a;
    asm("{.reg .u64 t; cvta.to.shared.u64 t,%1; cvt.u32.u64 %0,t;}" : "=r"(a) : "l"(p));
    return a;
}
__device__ __forceinline__ void ldsm4(uint32_t* r, uint32_t a) {
    asm volatile("ldmatrix.sync.aligned.m8n8.x4.shared.b16 {%0,%1,%2,%3},[%4];"
                 : "=r"(r[0]), "=r"(r[1]), "=r"(r[2]), "=r"(r[3]) : "r"(a));
}
__device__ __forceinline__ void ldsm4t(uint32_t* r, uint32_t a) {
    asm volatile("ldmatrix.sync.aligned.m8n8.x4.trans.shared.b16 {%0,%1,%2,%3},[%4];"
                 : "=r"(r[0]), "=r"(r[1]), "=r"(r[2]), "=r"(r[3]) : "r"(a));
}
__device__ __forceinline__ void mma_bf16(float* d, const uint32_t* a, uint32_t b0, uint32_t b1) {
    asm volatile("mma.sync.aligned.m16n8k16.row.col.f32.bf16.bf16.f32 "
                 "{%0,%1,%2,%3},{%4,%5,%6,%7},{%8,%9},{%0,%1,%2,%3};"
                 : "+f"(d[0]), "+f"(d[1]), "+f"(d[2]), "+f"(d[3])
                 : "r"(a[0]), "r"(a[1]), "r"(a[2]), "r"(a[3]), "r"(b0), "r"(b1));
}
// split f32 pair (a=even k, b=odd k) into bf16x2 hi word + bf16x2 lo (residual) word
__device__ __forceinline__ void split_pair(float a, float b, uint32_t& hw, uint32_t& lw) {
    __nv_bfloat16 ha = __float2bfloat16(a);
    __nv_bfloat16 hb = __float2bfloat16(b);
    float ra = a - __bfloat162float(ha);
    float rb = b - __bfloat162float(hb);
    __nv_bfloat162 h2; h2.x = ha; h2.y = hb;      // .x = low half = even k
    hw = *reinterpret_cast<uint32_t*>(&h2);
    asm("cvt.rn.bf16x2.f32 %0,%1,%2;" : "=r"(lw) : "f"(rb), "f"(ra));  // hi=rb, lo=ra
}
__device__ __forceinline__ float silu_f(float v) { return v / (1.0f + __expf(-v)); }

__global__ __launch_bounds__(NTH, 1)
void dipole_hmma_kernel(const float* __restrict__ x,
                        const float* __restrict__ w1s,
                        const float* __restrict__ w1v,
                        const float* __restrict__ w2s,
                        const float* __restrict__ w2v,
                        float* __restrict__ out,
                        int nrows)
{
    extern __shared__ char sm[];
    const uint32_t sb = s2u(sm);
    const int tid  = threadIdx.x;
    const int wid  = tid >> 5;
    const int lane = tid & 31;
    const int r0   = blockIdx.x * TILE_M;

    // shared accumulator file:
    //   S warps (wid<4): acc[j*4+d], j=0..15 n-tiles (cols 8j..8j+7), rows m16 @ wid*16
    //   V warps (wid>=4): acc[(b*8+j)*4+d], b=0..2 m-blocks, j=0..7 n-tiles
    float acc[96];
    #pragma unroll
    for (int j = 0; j < 96; ++j) acc[j] = 0.f;

    for (int c = 0; c < NCH; ++c) {
        // ======== staging: load f32, split into bf16 hi/lo tiles ========
        {   // xs: 4 threads/row, 16 consecutive k each
            int row = tid >> 2, q = tid & 3;
            int g = r0 + row; bool rv = g < nrows;
            const float4* p = (const float4*)(x + (size_t)g * 1024 + c * 64 + q * 16);
            uint32_t off = (uint32_t)(row * 144 + q * 32);
            #pragma unroll
            for (int u = 0; u < 4; ++u) {
                float4 f = rv ? __ldg(p + u) : make_float4(0.f,0.f,0.f,0.f);
                uint32_t h0,l0,h1,l1;
                split_pair(f.x, f.y, h0, l0);
                split_pair(f.z, f.w, h1, l1);
                *(uint32_t*)(sm + SM_AS_H + off + u*8)     = h0;
                *(uint32_t*)(sm + SM_AS_H + off + u*8 + 4) = h1;
                *(uint32_t*)(sm + SM_AS_L + off + u*8)     = l0;
                *(uint32_t*)(sm + SM_AS_L + off + u*8 + 4) = l1;
            }
        }
        if (tid < 192) {   // xv: thread per (comp, row), gathers 64 strided values
            int i = tid >> 6, row = tid & 63;
            int g = r0 + row; bool rv = g < nrows;
            const float* p = x + (size_t)g * 1024 + 256 + (size_t)(c * 64) * 3 + i;
            uint32_t off = (uint32_t)((i * 64 + row) * 144);
            #pragma unroll
            for (int kp = 0; kp < 32; ++kp) {
                float a = rv ? __ldg(p + 6*kp)     : 0.f;
                float b = rv ? __ldg(p + 6*kp + 3) : 0.f;
                uint32_t hw, lw; split_pair(a, b, hw, lw);
                *(uint32_t*)(sm + SM_AV_H + off + kp*4) = hw;
                *(uint32_t*)(sm + SM_AV_L + off + kp*4) = lw;
            }
        }
        {   // w1s chunk: [64 k][128 n]
            int kr = tid >> 2, nq = tid & 3;
            const float4* p = (const float4*)(w1s + (size_t)(c*64 + kr) * 128 + nq * 32);
            uint32_t off = (uint32_t)(kr * 272 + nq * 64);
            #pragma unroll
            for (int u = 0; u < 8; ++u) {
                float4 f = __ldg(p + u);
                uint32_t h0,l0,h1,l1;
                split_pair(f.x, f.y, h0, l0);
                split_pair(f.z, f.w, h1, l1);
                *(uint32_t*)(sm + SM_BS_H + off + u*8)     = h0;
                *(uint32_t*)(sm + SM_BS_H + off + u*8 + 4) = h1;
                *(uint32_t*)(sm + SM_BS_L + off + u*8)     = l0;
                *(uint32_t*)(sm + SM_BS_L + off + u*8 + 4) = l1;
            }
        }
        {   // w1v chunk: [64 k][64 n]
            int kr = tid >> 2, nq = tid & 3;
            const float4* p = (const float4*)(w1v + (size_t)(c*64 + kr) * 64 + nq * 16);
            uint32_t off = (uint32_t)(kr * 144 + nq * 32);
            #pragma unroll
            for (int u = 0; u < 4; ++u) {
                float4 f = __ldg(p + u);
                uint32_t h0,l0,h1,l1;
                split_pair(f.x, f.y, h0, l0);
                split_pair(f.z, f.w, h1, l1);
                *(uint32_t*)(sm + SM_BV_H + off + u*8)     = h0;
                *(uint32_t*)(sm + SM_BV_H + off + u*8 + 4) = h1;
                *(uint32_t*)(sm + SM_BV_L + off + u*8)     = l0;
                *(uint32_t*)(sm + SM_BV_L + off + u*8 + 4) = l1;
            }
        }
        __syncthreads();

        // ======== MMA phase ========
        if (wid < 4) {
            const int m0 = wid * 16;
            #pragma unroll 1
            for (int ks = 0; ks < 4; ++ks) {
                uint32_t arow = (uint32_t)(m0 + (lane & 7) + ((lane >> 3) & 1) * 8);
                uint32_t aoff = arow * 144 + ks * 32 + (lane >> 4) * 16;
                uint32_t ah[4], al[4];
                ldsm4(ah, sb + SM_AS_H + aoff);
                ldsm4(al, sb + SM_AS_L + aoff);
                uint32_t brow = (uint32_t)(ks * 16 + (lane & 7) + ((lane >> 3) & 1) * 8);
                #pragma unroll
                for (int t = 0; t < 8; ++t) {
                    uint32_t boff = brow * 272 + t * 32 + (lane >> 4) * 16;
                    uint32_t bh[4], bl[4];
                    ldsm4t(bh, sb + SM_BS_H + boff);
                    ldsm4t(bl, sb + SM_BS_L + boff);
                    mma_bf16(&acc[(2*t)*4],   ah, bh[0], bh[1]);
                    mma_bf16(&acc[(2*t+1)*4], ah, bh[2], bh[3]);
                    mma_bf16(&acc[(2*t)*4],   ah, bl[0], bl[1]);
                    mma_bf16(&acc[(2*t+1)*4], ah, bl[2], bl[3]);
                    mma_bf16(&acc[(2*t)*4],   al, bh[0], bh[1]);
                    mma_bf16(&acc[(2*t+1)*4], al, bh[2], bh[3]);
                }
            }
        } else {
            const int sb0 = (wid - 4) * 3;
            #pragma unroll 1
            for (int ks = 0; ks < 4; ++ks) {
                uint32_t Ah[3][4], Al[3][4];
                #pragma unroll
                for (int b = 0; b < 3; ++b) {
                    uint32_t arow = (uint32_t)((sb0 + b) * 16 + (lane & 7) + ((lane >> 3) & 1) * 8);
                    uint32_t aoff = arow * 144 + ks * 32 + (lane >> 4) * 16;
                    ldsm4(Ah[b], sb + SM_AV_H + aoff);
                    ldsm4(Al[b], sb + SM_AV_L + aoff);
                }
                uint32_t brow = (uint32_t)(ks * 16 + (lane & 7) + ((lane >> 3) & 1) * 8);
                #pragma unroll
                for (int t = 0; t < 4; ++t) {
                    uint32_t boff = brow * 144 + t * 32 + (lane >> 4) * 16;
                    uint32_t bh[4], bl[4];
                    ldsm4t(bh, sb + SM_BV_H + boff);
                    ldsm4t(bl, sb + SM_BV_L + boff);
                    #pragma unroll
                    for (int b = 0; b < 3; ++b) {
                        mma_bf16(&acc[(b*8 + 2*t)*4],   Ah[b], bh[0], bh[1]);
                        mma_bf16(&acc[(b*8 + 2*t+1)*4], Ah[b], bh[2], bh[3]);
                        mma_bf16(&acc[(b*8 + 2*t)*4],   Ah[b], bl[0], bl[1]);
                        mma_bf16(&acc[(b*8 + 2*t+1)*4], Ah[b], bl[2], bl[3]);
                        mma_bf16(&acc[(b*8 + 2*t)*4],   Al[b], bh[0], bh[1]);
                        mma_bf16(&acc[(b*8 + 2*t+1)*4], Al[b], bh[2], bh[3]);
                    }
                }
            }
        }
        __syncthreads();
    }

    // ======== epilogue ========
    const float inv16 = 1.0f / 16.0f;
    const float inv8  = 0.125f;
    float* gsm = (float*)(sm + SM_G);   // [64][65]

    if (wid < 4) {
        int rA = wid * 16 + (lane >> 2);
        int rB = rA + 8;
        float sA = 0.f, sB = 0.f;
        #pragma unroll
        for (int j = 0; j < 8; ++j) {        // scalar cols 0..63
            int c0 = 8*j + (lane & 3) * 2;
            float w0 = __ldg(w2s + c0), w1 = __ldg(w2s + c0 + 1);
            sA += silu_f(acc[j*4+0] * inv16) * w0 + silu_f(acc[j*4+1] * inv16) * w1;
            sB += silu_f(acc[j*4+2] * inv16) * w0 + silu_f(acc[j*4+3] * inv16) * w1;
        }
        #pragma unroll
        for (int j = 0; j < 8; ++j) {        // gate cols 64..127 -> g smem
            int k0 = 8*j + (lane & 3) * 2;
            float w0 = __ldg(w2v + k0), w1 = __ldg(w2v + k0 + 1);
            gsm[rA * 65 + k0]     = silu_f(acc[(8+j)*4+0] * inv16) * w0;
            gsm[rA * 65 + k0 + 1] = silu_f(acc[(8+j)*4+1] * inv16) * w1;
            gsm[rB * 65 + k0]     = silu_f(acc[(8+j)*4+2] * inv16) * w0;
            gsm[rB * 65 + k0 + 1] = silu_f(acc[(8+j)*4+3] * inv16) * w1;
        }
        sA += __shfl_xor_sync(0xffffffffu, sA, 1);
        sA += __shfl_xor_sync(0xffffffffu, sA, 2);
        sB += __shfl_xor_sync(0xffffffffu, sB, 1);
        sB += __shfl_xor_sync(0xffffffffu, sB, 2);
        if ((lane & 3) == 0) {
            int gA = r0 + rA; if (gA < nrows) out[4*gA] = sA * inv8;
            int gB = r0 + rB; if (gB < nrows) out[4*gB] = sB * inv8;
        }
    }
    __syncthreads();
    if (wid >= 4) {
        const int sb0 = (wid - 4) * 3;
        #pragma unroll
        for (int b = 0; b < 3; ++b) {
            int sblk = sb0 + b;
            int i    = sblk >> 2;
            int rA   = (sblk & 3) * 16 + (lane >> 2);
            int rB   = rA + 8;
            float vA = 0.f, vB = 0.f;
            #pragma unroll
            for (int j = 0; j < 8; ++j) {
                int k0 = 8*j + (lane & 3) * 2;
                vA += gsm[rA * 65 + k0]     * (acc[(b*8+j)*4+0] * inv16)
                    + gsm[rA * 65 + k0 + 1] * (acc[(b*8+j)*4+1] * inv16);
                vB += gsm[rB * 65 + k0]     * (acc[(b*8+j)*4+2] * inv16)
                    + gsm[rB * 65 + k0 + 1] * (acc[(b*8+j)*4+3] * inv16);
            }
            vA += __shfl_xor_sync(0xffffffffu, vA, 1);
            vA += __shfl_xor_sync(0xffffffffu, vA, 2);
            vB += __shfl_xor_sync(0xffffffffu, vB, 1);
            vB += __shfl_xor_sync(0xffffffffu, vB, 2);
            if ((lane & 3) == 0) {
                int gA = r0 + rA; if (gA < nrows) out[4*gA + 1 + i] = vA * inv8;
                int gB = r0 + rB; if (gB < nrows) out[4*gB + 1 + i] = vB * inv8;
            }
        }
    }
}

extern "C" void kernel_launch(void* const* d_in, const int* in_sizes, int n_in,
                              void* d_out, int out_size)
{
    const float* x   = (const float*)d_in[0];
    const float* w1s = (const float*)d_in[1];
    const float* w1v = (const float*)d_in[2];
    const float* w2s = (const float*)d_in[3];
    const float* w2v = (const float*)d_in[4];
    float* out = (float*)d_out;

    int nrows  = in_sizes[0] / 1024;
    int blocks = (nrows + TILE_M - 1) / TILE_M;   // 1563

    cudaFuncSetAttribute(dipole_hmma_kernel,
                         cudaFuncAttributeMaxDynamicSharedMemorySize, SM_TOTAL);
    dipole_hmma_kernel<<<blocks, NTH, SM_TOTAL>>>(x, w1s, w1v, w2s, w2v, out, nrows);
}